// round 9
// baseline (speedup 1.0000x reference)
#include <cuda_runtime.h>
#include <cuda_fp16.h>
#include <cstdint>

#define NN 50000
#define EE 600000
#define GG 256
#define HH 128
#define SCAN_B 512
#define NP ((NN + SCAN_B - 1) / SCAN_B)   // 98
#define NTILES ((NN + 127) / 128)         // 391
#define TPB 512

// ---------------- scratch ----------------
__device__ __half g_x16[NN * HH];
__device__ __half g_tmp[NN * HH];
__device__ __half g_wh[3 * HH * HH];
__device__ __half g_wl[3 * HH * HH];
__device__ float g_dis[NN];
__device__ int   g_deg[NN];
__device__ int   g_row_off[NN + 1];
__device__ int   g_fill[NN];
__device__ int   g_src[EE];
__device__ float g_nrm[EE];
__device__ float g_cnt[GG];
__device__ int   g_part[NP];
__device__ int   g_idx64;
__device__ int   g_bar_count;
__device__ volatile int g_bar_gen;

// ---------------- software grid barrier (co-resident grid) ----------------
__device__ __forceinline__ void gsync(int grid, int* s_gen) {
    __threadfence();                       // publish this thread's writes
    __syncthreads();
    if (threadIdx.x == 0) {
        int target = *s_gen + 1;
        *s_gen = target;
        if (atomicAdd(&g_bar_count, 1) == grid - 1) {
            g_bar_count = 0;
            __threadfence();
            g_bar_gen = target;
        } else {
            while (g_bar_gen < target) { }
        }
    }
    __syncthreads();
}

__device__ __forceinline__ int idx_at(const void* p, long long i, int is64) {
    if (is64) return (int)((const long long*)p)[i];
    return ((const int*)p)[i];
}

// final exclusive CSR offset (cross-block partial applied inline; .cg reads)
__device__ __forceinline__ int roff(int j) {
    if (j == 0) return 0;
    int b = (j - 1) / SCAN_B;
    int v = __ldcg(&g_row_off[j]);
    return (b > 0) ? v + __ldcg(&g_part[b - 1]) : v;
}

// ---------------- mma helpers ----------------
__device__ __forceinline__ uint32_t smem_u32(const void* p) {
    return (uint32_t)__cvta_generic_to_shared(p);
}
__device__ __forceinline__ void ldsm_x4(uint32_t* r, uint32_t a) {
    asm volatile("ldmatrix.sync.aligned.m8n8.x4.shared.b16 {%0,%1,%2,%3}, [%4];\n"
                 : "=r"(r[0]), "=r"(r[1]), "=r"(r[2]), "=r"(r[3]) : "r"(a));
}
__device__ __forceinline__ void ldsm_x4_t(uint32_t* r, uint32_t a) {
    asm volatile("ldmatrix.sync.aligned.m8n8.x4.trans.shared.b16 {%0,%1,%2,%3}, [%4];\n"
                 : "=r"(r[0]), "=r"(r[1]), "=r"(r[2]), "=r"(r[3]) : "r"(a));
}
__device__ __forceinline__ void mma_f16(float* d, const uint32_t* a, uint32_t b0, uint32_t b1) {
    asm volatile(
        "mma.sync.aligned.m16n8k16.row.col.f32.f16.f16.f32 "
        "{%0,%1,%2,%3}, {%4,%5,%6,%7}, {%8,%9}, {%0,%1,%2,%3};\n"
        : "+f"(d[0]), "+f"(d[1]), "+f"(d[2]), "+f"(d[3])
        : "r"(a[0]), "r"(a[1]), "r"(a[2]), "r"(a[3]), "r"(b0), "r"(b1));
}

// L2-only row gather: 8 fp16 channels per lane
__device__ __forceinline__ float4 ld_row_cg(const __half* h, int node, int lane) {
    float2 r = __ldcg((const float2*)&h[(size_t)node * HH + lane * 4]);
    __half2 a = *(__half2*)&r.x;
    __half2 b = *(__half2*)&r.y;
    float2 fa = __half22float2(a), fb = __half22float2(b);
    return make_float4(fa.x, fa.y, fb.x, fb.y);
}

// ================= the one kernel =================
__global__ void __launch_bounds__(TPB) fused_kernel(
    const float* __restrict__ x,
    const float* __restrict__ W1, const float* __restrict__ b1,
    const float* __restrict__ W2, const float* __restrict__ b2,
    const float* __restrict__ W3, const float* __restrict__ b3,
    const void* __restrict__ ei, const void* __restrict__ bidx,
    float* __restrict__ out, int grid)
{
    __shared__ __half sA [128][32 + 8];
    __shared__ __half sWh[32][HH + 8];
    __shared__ __half sWl[32][HH + 8];
    __shared__ int wsum[16];
    __shared__ int s_gen;

    int tid  = threadIdx.x;
    int bid  = blockIdx.x;
    int NT   = grid * TPB;
    int gtid = bid * TPB + tid;
    int lane = tid & 31, wid = tid >> 5;

    if (tid == 0) s_gen = g_bar_gen;
    __syncthreads();

    // ---- P0a: zero + convert + detect ----
    if (gtid == 0) {
        const int* e32 = (const int*)ei;
        int all_zero = 1;
        for (int k = 1; k < 64; k += 2)
            if (e32[k] != 0) all_zero = 0;
        g_idx64 = all_zero;
    }
    for (int i = gtid; i < NN * HH / 4; i += NT) {
        float4 v = ((const float4*)x)[i];
        __half2* p = (__half2*)&g_x16[i * 4];
        p[0] = __floats2half2_rn(v.x, v.y);
        p[1] = __floats2half2_rn(v.z, v.w);
    }
    for (int i = gtid; i < 3 * HH * HH; i += NT) {
        int which = i >> 14;
        int j = i & (HH * HH - 1);
        const float* W = (which == 0) ? W1 : (which == 1) ? W2 : W3;
        float w = W[j];
        __half h = __float2half_rn(w);
        g_wh[i] = h;
        g_wl[i] = __float2half_rn(w - __half2float(h));
    }
    for (int i = gtid; i < GG * HH; i += NT) out[i] = 0.0f;
    for (int i = gtid; i < NN; i += NT) { g_deg[i] = 0; g_fill[i] = 0; }
    for (int i = gtid; i < GG; i += NT) g_cnt[i] = 0.0f;
    gsync(grid, &s_gen);                                        // B1

    // ---- P0b: degree histogram + graph counts ----
    {
        int is64 = __ldcg(&g_idx64);
        for (int e = gtid; e < EE; e += NT)
            atomicAdd(&g_deg[idx_at(ei, (long long)EE + e, is64)], 1);
        for (int i = gtid; i < NN; i += NT)
            atomicAdd(&g_cnt[idx_at(bidx, i, is64)], 1.0f);
    }
    gsync(grid, &s_gen);                                        // B2

    // ---- P1a: per-chunk scans (+ deg_inv_sqrt fused) ----
    for (int c = bid; c < NP; c += grid) {
        int i = c * SCAN_B + tid;
        int v = (i < NN) ? __ldcg(&g_deg[i]) : 0;
        if (i < NN) g_dis[i] = rsqrtf((float)v + 1.0f);
        int xx = v;
        #pragma unroll
        for (int off = 1; off < 32; off <<= 1) {
            int y = __shfl_up_sync(0xffffffffu, xx, off);
            if (lane >= off) xx += y;
        }
        if (lane == 31) wsum[wid] = xx;
        __syncthreads();
        if (wid == 0) {
            int s = (lane < 16) ? wsum[lane] : 0;
            #pragma unroll
            for (int off = 1; off < 16; off <<= 1) {
                int y = __shfl_up_sync(0xffffffffu, s, off);
                if (lane >= off) s += y;
            }
            if (lane < 16) wsum[lane] = s;
        }
        __syncthreads();
        int inc = xx + ((wid > 0) ? wsum[wid - 1] : 0);
        if (i < NN) g_row_off[i + 1] = inc;
        if (tid == SCAN_B - 1) g_part[c] = inc;
        __syncthreads();
    }
    gsync(grid, &s_gen);                                        // B3

    // ---- P1b: block 0 scans NP partials in place ----
    if (bid == 0) {
        int xx = (tid < NP) ? __ldcg(&g_part[tid]) : 0;
        int v0 = xx;
        #pragma unroll
        for (int off = 1; off < 32; off <<= 1) {
            int y = __shfl_up_sync(0xffffffffu, xx, off);
            if (lane >= off) xx += y;
        }
        if (lane == 31) wsum[wid] = xx;
        __syncthreads();
        if (wid == 0) {
            int s = (lane < 16) ? wsum[lane] : 0;
            #pragma unroll
            for (int off = 1; off < 16; off <<= 1) {
                int y = __shfl_up_sync(0xffffffffu, s, off);
                if (lane >= off) s += y;
            }
            if (lane < 16) wsum[lane] = s;
        }
        __syncthreads();
        (void)v0;
        int inc = xx + ((wid > 0) ? wsum[wid - 1] : 0);
        if (tid < NP) g_part[tid] = inc;
    }
    gsync(grid, &s_gen);                                        // B4

    // ---- P2: CSR fill ----
    {
        int is64 = __ldcg(&g_idx64);
        for (int e = gtid; e < EE; e += NT) {
            int s = idx_at(ei, e, is64);
            int d = idx_at(ei, (long long)EE + e, is64);
            int p = roff(d) + atomicAdd(&g_fill[d], 1);
            g_src[p] = s;
            g_nrm[p] = __ldcg(&g_dis[s]) * __ldcg(&g_dis[d]);
        }
    }
    gsync(grid, &s_gen);                                        // B5

    // ---- layers ----
    int is64 = __ldcg(&g_idx64);
    for (int L = 0; L < 3; L++) {
        const __half* Wh = g_wh + L * HH * HH;
        const __half* Wl = g_wl + L * HH * HH;
        const float* bias = (L == 0) ? b1 : (L == 1) ? b2 : b3;

        // -- GEMM phase: tmp = x16 @ (Wh + Wl) --
        {
            int wm = wid & 3, wn = wid >> 2;   // 4 x 4 warp grid, warp tile 32x32
            for (int t = bid; t < NTILES; t += grid) {
                int m0 = t * 128;
                float d[2][4][4];
                #pragma unroll
                for (int a = 0; a < 2; a++)
                    #pragma unroll
                    for (int b = 0; b < 4; b++)
                        #pragma unroll
                        for (int c = 0; c < 4; c++) d[a][b][c] = 0.0f;

                for (int k0 = 0; k0 < HH; k0 += 32) {
                    {   // A tile: 128 rows x 32 k = 512 uint4 slots
                        int row = tid >> 2;
                        int q = tid & 3;
                        int m = m0 + row;
                        uint4 v = make_uint4(0,0,0,0);
                        if (m < NN) v = __ldcg((const uint4*)&g_x16[(size_t)m * HH + k0 + q * 8]);
                        *(uint4*)&sA[row][q * 8] = v;
                    }
                    {   // W tiles: 32 rows x 128 n = 512 uint4 slots each
                        int row = tid >> 4;
                        int q = tid & 15;
                        *(uint4*)&sWh[row][q * 8] = __ldcg((const uint4*)&Wh[(k0 + row) * HH + q * 8]);
                        *(uint4*)&sWl[row][q * 8] = __ldcg((const uint4*)&Wl[(k0 + row) * HH + q * 8]);
                    }
                    __syncthreads();

                    #pragma unroll
                    for (int kk = 0; kk < 32; kk += 16) {
                        uint32_t af[2][4];
                        #pragma unroll
                        for (int mi = 0; mi < 2; mi++) {
                            int r = wm * 32 + mi * 16 + (lane & 15);
                            int c = kk + (lane >> 4) * 8;
                            ldsm_x4(af[mi], smem_u32(&sA[r][c]));
                        }
                        #pragma unroll
                        for (int ni = 0; ni < 2; ni++) {
                            uint32_t bh[4], bl[4];
                            int rk = kk + (lane & 15);
                            int cn = wn * 32 + ni * 16 + (lane >> 4) * 8;
                            ldsm_x4_t(bh, smem_u32(&sWh[rk][cn]));
                            ldsm_x4_t(bl, smem_u32(&sWl[rk][cn]));
                            #pragma unroll
                            for (int mi = 0; mi < 2; mi++) {
                                #pragma unroll
                                for (int h = 0; h < 2; h++) {
                                    int nj = ni * 2 + h;
                                    mma_f16(d[mi][nj], af[mi], bh[h*2], bh[h*2+1]);
                                    mma_f16(d[mi][nj], af[mi], bl[h*2], bl[h*2+1]);
                                }
                            }
                        }
                    }
                    __syncthreads();
                }

                #pragma unroll
                for (int mi = 0; mi < 2; mi++) {
                    #pragma unroll
                    for (int nj = 0; nj < 4; nj++) {
                        int col = wn * 32 + nj * 8 + (lane & 3) * 2;
                        int r0 = m0 + wm * 32 + mi * 16 + (lane >> 2);
                        if (r0 < NN)
                            *(__half2*)&g_tmp[(size_t)r0 * HH + col] = __floats2half2_rn(d[mi][nj][0], d[mi][nj][1]);
                        int r1 = r0 + 8;
                        if (r1 < NN)
                            *(__half2*)&g_tmp[(size_t)r1 * HH + col] = __floats2half2_rn(d[mi][nj][2], d[mi][nj][3]);
                    }
                }
            }
        }
        gsync(grid, &s_gen);                                    // B6/B8/B10

        // -- AGG phase: one warp per node --
        {
            int nwarps = grid * (TPB / 32);
            for (int n = bid * (TPB / 32) + wid; n < NN; n += nwarps) {
                float dn = __ldcg(&g_dis[n]);
                float self = dn * dn;

                float4 acc = ld_row_cg(g_tmp, n, lane);
                acc.x *= self; acc.y *= self; acc.z *= self; acc.w *= self;

                int e  = roff(n);
                int s1 = roff(n + 1);
                for (; e + 3 < s1; e += 4) {
                    int   sA0 = __ldcg(&g_src[e]),   sB = __ldcg(&g_src[e+1]);
                    int   sC  = __ldcg(&g_src[e+2]), sD = __ldcg(&g_src[e+3]);
                    float nA = __ldcg(&g_nrm[e]),   nB = __ldcg(&g_nrm[e+1]);
                    float nC = __ldcg(&g_nrm[e+2]), nD = __ldcg(&g_nrm[e+3]);
                    float4 vA = ld_row_cg(g_tmp, sA0, lane);
                    float4 vB = ld_row_cg(g_tmp, sB, lane);
                    float4 vC = ld_row_cg(g_tmp, sC, lane);
                    float4 vD = ld_row_cg(g_tmp, sD, lane);
                    acc.x += vA.x*nA + vB.x*nB + vC.x*nC + vD.x*nD;
                    acc.y += vA.y*nA + vB.y*nB + vC.y*nC + vD.y*nD;
                    acc.z += vA.z*nA + vB.z*nB + vC.z*nC + vD.z*nD;
                    acc.w += vA.w*nA + vB.w*nB + vC.w*nC + vD.w*nD;
                }
                for (; e < s1; e++) {
                    int   s   = __ldcg(&g_src[e]);
                    float nrm = __ldcg(&g_nrm[e]);
                    float4 v  = ld_row_cg(g_tmp, s, lane);
                    acc.x += v.x * nrm; acc.y += v.y * nrm;
                    acc.z += v.z * nrm; acc.w += v.w * nrm;
                }

                float4 bb = *reinterpret_cast<const float4*>(&bias[lane * 4]);
                acc.x = fmaxf(acc.x + bb.x, 0.0f);
                acc.y = fmaxf(acc.y + bb.y, 0.0f);
                acc.z = fmaxf(acc.z + bb.z, 0.0f);
                acc.w = fmaxf(acc.w + bb.w, 0.0f);

                if (L < 2) {
                    __half2* p = (__half2*)&g_x16[(size_t)n * HH + lane * 4];
                    p[0] = __floats2half2_rn(acc.x, acc.y);
                    p[1] = __floats2half2_rn(acc.z, acc.w);
                } else {
                    int g = idx_at(bidx, n, is64);
                    float ic = 1.0f / fmaxf(__ldcg(&g_cnt[g]), 1.0f);
                    float* p = &out[g * HH + lane * 4];
                    atomicAdd(p + 0, acc.x * ic);
                    atomicAdd(p + 1, acc.y * ic);
                    atomicAdd(p + 2, acc.z * ic);
                    atomicAdd(p + 3, acc.w * ic);
                }
            }
        }
        if (L < 2) gsync(grid, &s_gen);                         // B7/B9
    }
}

// ---------------- launch ----------------
extern "C" void kernel_launch(void* const* d_in, const int* in_sizes, int n_in,
                              void* d_out, int out_size)
{
    const float* x    = (const float*)d_in[0];
    const float* W1   = (const float*)d_in[1];
    const float* b1   = (const float*)d_in[2];
    const float* W2   = (const float*)d_in[3];
    const float* b2   = (const float*)d_in[4];
    const float* W3   = (const float*)d_in[5];
    const float* b3   = (const float*)d_in[6];
    const void*  ei   = d_in[7];
    const void*  bidx = d_in[8];
    float* out = (float*)d_out;
    (void)in_sizes; (void)n_in; (void)out_size;

    int sm = 0;
    cudaDeviceGetAttribute(&sm, cudaDevAttrMultiProcessorCount, 0);
    if (sm <= 0) sm = 148;

    fused_kernel<<<sm, TPB>>>(x, W1, b1, W2, b2, W3, b3, ei, bidx, out, sm);
}

// round 10
// speedup vs baseline: 1.6312x; 1.6312x over previous
#include <cuda_runtime.h>
#include <cuda_fp16.h>
#include <cstdint>

#define NN 50000
#define EE 600000
#define GG 256
#define HH 128
#define SCAN_B 512
#define NP ((NN + SCAN_B - 1) / SCAN_B)   // 98

// ---------------- scratch ----------------
__device__ __half g_x16[NN * HH];     // fp16 activations (GEMM input)
__device__ __half g_tmp[NN * HH];     // fp16 GEMM output
__device__ __half g_wh[3 * HH * HH];  // fp16 weights hi  [k][n]
__device__ __half g_wl[3 * HH * HH];  // fp16 weights lo  [k][n]
__device__ float g_dis[NN];
__device__ int   g_deg[NN];
__device__ int   g_row_off[NN + 1];   // block-local inclusive scan
__device__ int   g_fill[NN];
__device__ int   g_src_sorted[EE];
__device__ float g_norm_sorted[EE];
__device__ float g_cnt[GG];           // nodes per graph (batch histogram)
__device__ int   g_part[NP];          // inclusive partials per scan block
__device__ int   g_done;              // scan last-block counter
__device__ int   g_idx64;

__device__ __forceinline__ int idx_at(const void* p, long long i) {
    if (g_idx64) return (int)((const long long*)p)[i];
    return ((const int*)p)[i];
}

// final exclusive CSR offset for node j (applies cross-block partial inline)
__device__ __forceinline__ int roff(int j) {
    if (j == 0) return 0;
    int b = (j - 1) / SCAN_B;
    int v = g_row_off[j];
    return (b > 0) ? v + g_part[b - 1] : v;
}

// ---------------- init (+ dtype detect) ----------------
__global__ void init_kernel(float* __restrict__ out, const int* __restrict__ ei_raw) {
    int i = blockIdx.x * blockDim.x + threadIdx.x;
    if (i == 0) {
        int all_zero = 1;
        for (int k = 1; k < 64; k += 2)
            if (ei_raw[k] != 0) all_zero = 0;
        g_idx64 = all_zero;
        g_done = 0;
    }
    if (i < NN) { g_deg[i] = 0; g_fill[i] = 0; }
    if (i < GG * HH) out[i] = 0.0f;
    if (i < GG) g_cnt[i] = 0.0f;
}

// ---------------- merged: x->fp16, W->fp16 hi/lo, deg histogram, batch counts ----------------
__global__ void cvt_deg_kernel(const float* __restrict__ x,
                               const float* __restrict__ W1,
                               const float* __restrict__ W2,
                               const float* __restrict__ W3,
                               const void* __restrict__ edge_index,
                               const void* __restrict__ batch_idx) {
    int i = blockIdx.x * blockDim.x + threadIdx.x;
    if (i < NN * HH / 4) {
        float4 v = ((const float4*)x)[i];
        __half2* p = (__half2*)&g_x16[i * 4];
        p[0] = __floats2half2_rn(v.x, v.y);
        p[1] = __floats2half2_rn(v.z, v.w);
    }
    if (i < 3 * HH * HH) {
        int which = i >> 14;
        int j = i & (HH * HH - 1);
        const float* W = (which == 0) ? W1 : (which == 1) ? W2 : W3;
        float w = W[j];
        __half h = __float2half_rn(w);
        g_wh[i] = h;
        g_wl[i] = __float2half_rn(w - __half2float(h));
    }
    if (i < EE) {
        atomicAdd(&g_deg[idx_at(edge_index, (long long)EE + i)], 1);
    }
    if (i < NN) {
        atomicAdd(&g_cnt[idx_at(batch_idx, i)], 1.0f);
    }
}

// ---------------- fused scan: per-block scan, last block scans partials ----------------
__global__ void scan_kernel() {
    __shared__ int wsum[16];
    __shared__ int s_last;
    int b = blockIdx.x, t = threadIdx.x;
    int i = b * SCAN_B + t;
    int lane = t & 31, w = t >> 5;

    int v = (i < NN) ? g_deg[i] : 0;
    if (i < NN) g_dis[i] = rsqrtf((float)v + 1.0f);
    int x = v;
    #pragma unroll
    for (int off = 1; off < 32; off <<= 1) {
        int y = __shfl_up_sync(0xffffffffu, x, off);
        if (lane >= off) x += y;
    }
    if (lane == 31) wsum[w] = x;
    __syncthreads();
    if (w == 0) {
        int s = (lane < 16) ? wsum[lane] : 0;
        #pragma unroll
        for (int off = 1; off < 16; off <<= 1) {
            int y = __shfl_up_sync(0xffffffffu, s, off);
            if (lane >= off) s += y;
        }
        if (lane < 16) wsum[lane] = s;
    }
    __syncthreads();
    int inc = x + ((w > 0) ? wsum[w - 1] : 0);
    if (i < NN) g_row_off[i + 1] = inc;
    if (t == SCAN_B - 1) g_part[b] = inc;

    // last block to finish performs the partial scan (scan2 logic)
    __threadfence();
    __syncthreads();
    if (t == 0) s_last = (atomicAdd(&g_done, 1) == gridDim.x - 1) ? 1 : 0;
    __syncthreads();
    if (!s_last) return;

    if (t < 128) {
        int xx = (t < NP) ? g_part[t] : 0;
        #pragma unroll
        for (int off = 1; off < 32; off <<= 1) {
            int y = __shfl_up_sync(0xffffffffu, xx, off);
            if (lane >= off) xx += y;
        }
        if (lane == 31) wsum[w] = xx;
        __syncwarp();
        // cross-warp combine over the 4 participating warps
        __syncthreads();
        if (w == 0 && lane < 4) {
            int s = wsum[lane];
            #pragma unroll
            for (int off = 1; off < 4; off <<= 1) {
                int y = __shfl_up_sync(0x0000000fu, s, off);
                if (lane >= off) s += y;
            }
            wsum[lane] = s;
        }
        __syncthreads();
        int inc2 = xx + ((w > 0) ? wsum[w - 1] : 0);
        if (t < NP) g_part[t] = inc2;
    } else {
        __syncthreads();
        __syncthreads();
    }
}

// ---------------- CSR fill ----------------
__global__ void fill_kernel(const void* __restrict__ edge_index) {
    int e = blockIdx.x * blockDim.x + threadIdx.x;
    if (e >= EE) return;
    int s = idx_at(edge_index, e);
    int d = idx_at(edge_index, (long long)EE + e);
    int p = roff(d) + atomicAdd(&g_fill[d], 1);
    g_src_sorted[p]  = s;
    g_norm_sorted[p] = g_dis[s] * g_dis[d];
}

// ---------------- mma helpers ----------------
__device__ __forceinline__ uint32_t smem_u32(const void* p) {
    return (uint32_t)__cvta_generic_to_shared(p);
}
__device__ __forceinline__ void ldsm_x4(uint32_t* r, uint32_t a) {
    asm volatile("ldmatrix.sync.aligned.m8n8.x4.shared.b16 {%0,%1,%2,%3}, [%4];\n"
                 : "=r"(r[0]), "=r"(r[1]), "=r"(r[2]), "=r"(r[3]) : "r"(a));
}
__device__ __forceinline__ void ldsm_x4_t(uint32_t* r, uint32_t a) {
    asm volatile("ldmatrix.sync.aligned.m8n8.x4.trans.shared.b16 {%0,%1,%2,%3}, [%4];\n"
                 : "=r"(r[0]), "=r"(r[1]), "=r"(r[2]), "=r"(r[3]) : "r"(a));
}
__device__ __forceinline__ void mma_f16(float* d, const uint32_t* a, uint32_t b0, uint32_t b1) {
    asm volatile(
        "mma.sync.aligned.m16n8k16.row.col.f32.f16.f16.f32 "
        "{%0,%1,%2,%3}, {%4,%5,%6,%7}, {%8,%9}, {%0,%1,%2,%3};\n"
        : "+f"(d[0]), "+f"(d[1]), "+f"(d[2]), "+f"(d[3])
        : "r"(a[0]), "r"(a[1]), "r"(a[2]), "r"(a[3]), "r"(b0), "r"(b1));
}

// ---------------- fp16 2-term tensor-core GEMM: C = A*(Wh + Wl) ----------------
#define KC 32
__global__ __launch_bounds__(256) void gemm_f16_kernel(
    const __half* __restrict__ A,
    const __half* __restrict__ Wh, const __half* __restrict__ Wl,
    __half* __restrict__ C, int M)
{
    __shared__ __half sA [128][KC + 8];
    __shared__ __half sWh[KC][HH + 8];
    __shared__ __half sWl[KC][HH + 8];

    int tid = threadIdx.x;
    int wid = tid >> 5, lane = tid & 31;
    int wm = wid & 3, wn = wid >> 2;
    int m0 = blockIdx.x * 128;

    float d[2][8][4];
    #pragma unroll
    for (int a = 0; a < 2; a++)
        #pragma unroll
        for (int b = 0; b < 8; b++)
            #pragma unroll
            for (int c = 0; c < 4; c++) d[a][b][c] = 0.0f;

    for (int k0 = 0; k0 < HH; k0 += KC) {
        #pragma unroll
        for (int it = 0; it < 2; it++) {
            int slot = tid + it * 256;      // 512 slots: 128 rows x 4 uint4
            int row = slot >> 2;
            int q = slot & 3;
            int m = m0 + row;
            uint4 v = make_uint4(0,0,0,0);
            if (m < M) v = *(const uint4*)&A[(size_t)m * HH + k0 + q * 8];
            *(uint4*)&sA[row][q * 8] = v;
        }
        #pragma unroll
        for (int it = 0; it < 2; it++) {
            int slot = tid + it * 256;      // 512 slots: 32 rows x 16 uint4
            int row = slot >> 4;
            int q = slot & 15;
            *(uint4*)&sWh[row][q * 8] = *(const uint4*)&Wh[(k0 + row) * HH + q * 8];
            *(uint4*)&sWl[row][q * 8] = *(const uint4*)&Wl[(k0 + row) * HH + q * 8];
        }
        __syncthreads();

        #pragma unroll
        for (int kk = 0; kk < KC; kk += 16) {
            uint32_t af[2][4];
            #pragma unroll
            for (int mi = 0; mi < 2; mi++) {
                int r = wm * 32 + mi * 16 + (lane & 15);
                int c = kk + (lane >> 4) * 8;
                ldsm_x4(af[mi], smem_u32(&sA[r][c]));
            }
            #pragma unroll
            for (int ni = 0; ni < 4; ni++) {
                uint32_t bh[4], bl[4];
                int rk = kk + (lane & 15);
                int cn = wn * 64 + ni * 16 + (lane >> 4) * 8;
                ldsm_x4_t(bh, smem_u32(&sWh[rk][cn]));
                ldsm_x4_t(bl, smem_u32(&sWl[rk][cn]));
                #pragma unroll
                for (int mi = 0; mi < 2; mi++) {
                    #pragma unroll
                    for (int h = 0; h < 2; h++) {
                        int nj = ni * 2 + h;
                        mma_f16(d[mi][nj], af[mi], bh[h*2], bh[h*2+1]);
                        mma_f16(d[mi][nj], af[mi], bl[h*2], bl[h*2+1]);
                    }
                }
            }
        }
        __syncthreads();
    }

    #pragma unroll
    for (int mi = 0; mi < 2; mi++) {
        #pragma unroll
        for (int nj = 0; nj < 8; nj++) {
            int col = wn * 64 + nj * 8 + (lane & 3) * 2;
            int r0 = m0 + wm * 32 + mi * 16 + (lane >> 2);
            if (r0 < M)
                *(__half2*)&C[(size_t)r0 * HH + col] = __floats2half2_rn(d[mi][nj][0], d[mi][nj][1]);
            int r1 = r0 + 8;
            if (r1 < M)
                *(__half2*)&C[(size_t)r1 * HH + col] = __floats2half2_rn(d[mi][nj][2], d[mi][nj][3]);
        }
    }
}

// ---------------- aggregation (fp16 gather -> fp16 out / scaled pool) ----------------
__device__ __forceinline__ float4 ld_row_h(const __half* h, int node, int lane) {
    const __half2* p = (const __half2*)&h[(size_t)node * HH + lane * 4];
    float2 a = __half22float2(p[0]);
    float2 b = __half22float2(p[1]);
    return make_float4(a.x, a.y, b.x, b.y);
}

__global__ void agg_kernel(const __half* __restrict__ h,
                           const float* __restrict__ bias,
                           __half* __restrict__ out16,
                           int do_pool,
                           const void* __restrict__ batch_idx,
                           float* __restrict__ pool)
{
    int warp = (blockIdx.x * blockDim.x + threadIdx.x) >> 5;
    int lane = threadIdx.x & 31;
    if (warp >= NN) return;
    int n = warp;

    float dn = g_dis[n];
    float self = dn * dn;

    float4 acc = ld_row_h(h, n, lane);
    acc.x *= self; acc.y *= self; acc.z *= self; acc.w *= self;

    int e  = roff(n);
    int s1 = roff(n + 1);
    for (; e + 3 < s1; e += 4) {
        int   sA = g_src_sorted[e],   sB = g_src_sorted[e+1];
        int   sC = g_src_sorted[e+2], sD = g_src_sorted[e+3];
        float nA = g_norm_sorted[e],   nB = g_norm_sorted[e+1];
        float nC = g_norm_sorted[e+2], nD = g_norm_sorted[e+3];
        float4 vA = ld_row_h(h, sA, lane);
        float4 vB = ld_row_h(h, sB, lane);
        float4 vC = ld_row_h(h, sC, lane);
        float4 vD = ld_row_h(h, sD, lane);
        acc.x += vA.x*nA + vB.x*nB + vC.x*nC + vD.x*nD;
        acc.y += vA.y*nA + vB.y*nB + vC.y*nC + vD.y*nD;
        acc.z += vA.z*nA + vB.z*nB + vC.z*nC + vD.z*nD;
        acc.w += vA.w*nA + vB.w*nB + vC.w*nC + vD.w*nD;
    }
    for (; e < s1; e++) {
        int   s   = g_src_sorted[e];
        float nrm = g_norm_sorted[e];
        float4 v  = ld_row_h(h, s, lane);
        acc.x += v.x * nrm; acc.y += v.y * nrm;
        acc.z += v.z * nrm; acc.w += v.w * nrm;
    }

    float4 bb = *reinterpret_cast<const float4*>(&bias[lane * 4]);
    acc.x = fmaxf(acc.x + bb.x, 0.0f);
    acc.y = fmaxf(acc.y + bb.y, 0.0f);
    acc.z = fmaxf(acc.z + bb.z, 0.0f);
    acc.w = fmaxf(acc.w + bb.w, 0.0f);

    if (!do_pool) {
        __half2* p = (__half2*)&out16[(size_t)n * HH + lane * 4];
        p[0] = __floats2half2_rn(acc.x, acc.y);
        p[1] = __floats2half2_rn(acc.z, acc.w);
    } else {
        int g = idx_at(batch_idx, n);
        float ic = 1.0f / fmaxf(g_cnt[g], 1.0f);   // mean pool, no divide kernel
        float* p = &pool[g * HH + lane * 4];
        atomicAdd(p + 0, acc.x * ic);
        atomicAdd(p + 1, acc.y * ic);
        atomicAdd(p + 2, acc.z * ic);
        atomicAdd(p + 3, acc.w * ic);
    }
}

// ---------------- launch ----------------
extern "C" void kernel_launch(void* const* d_in, const int* in_sizes, int n_in,
                              void* d_out, int out_size)
{
    const float* x    = (const float*)d_in[0];
    const float* W1   = (const float*)d_in[1];
    const float* b1   = (const float*)d_in[2];
    const float* W2   = (const float*)d_in[3];
    const float* b2   = (const float*)d_in[4];
    const float* W3   = (const float*)d_in[5];
    const float* b3   = (const float*)d_in[6];
    const void*  ei   = d_in[7];
    const void*  bidx = d_in[8];
    float* out = (float*)d_out;

    __half *x16, *tmp, *wh, *wl;
    cudaGetSymbolAddress((void**)&x16, g_x16);
    cudaGetSymbolAddress((void**)&tmp, g_tmp);
    cudaGetSymbolAddress((void**)&wh,  g_wh);
    cudaGetSymbolAddress((void**)&wl,  g_wl);
    (void)in_sizes; (void)n_in; (void)out_size;

    const int T = 256;
    int gemm_blocks = (NN + 127) / 128;
    int agg_blocks  = (NN * 32 + T - 1) / T;
    int cvt_blocks  = (NN * HH / 4 + T - 1) / T;   // covers all cvt_deg ranges

    init_kernel<<<(NN + T - 1) / T, T>>>(out, (const int*)ei);             // 0
    cvt_deg_kernel<<<cvt_blocks, T>>>(x, W1, W2, W3, ei, bidx);            // 1
    scan_kernel<<<NP, SCAN_B>>>();                                         // 2
    fill_kernel<<<(EE + T - 1) / T, T>>>(ei);                              // 3
    gemm_f16_kernel<<<gemm_blocks, 256>>>(x16, wh, wl, tmp, NN);           // 4
    agg_kernel<<<agg_blocks, T>>>(tmp, b1, x16, 0, bidx, out);             // 5 (profiled)

    gemm_f16_kernel<<<gemm_blocks, 256>>>(x16, wh + HH*HH, wl + HH*HH, tmp, NN);
    agg_kernel<<<agg_blocks, T>>>(tmp, b2, x16, 0, bidx, out);

    gemm_f16_kernel<<<gemm_blocks, 256>>>(x16, wh + 2*HH*HH, wl + 2*HH*HH, tmp, NN);
    agg_kernel<<<agg_blocks, T>>>(tmp, b3, x16, 1, bidx, out);
}